// round 16
// baseline (speedup 1.0000x reference)
#include <cuda_runtime.h>
#include <cuda_fp16.h>
#include <math.h>

#define BB 2
#define LLE 1024
#define DDIM 1024
#define HH 16
#define DK 64
#define ROWS (BB*LLE)            // 2048
#define OUT_ELEMS (BB*LLE*DDIM)  // 2,097,152

// Scratch (allocation-free rule: __device__ globals)
__device__ __half g_qnh [ROWS*DDIM];     // LN(query) fp16
__device__ __half g_xh  [ROWS*DDIM];     // query fp16
__device__ __half g_wh  [4*DDIM*DDIM];   // Wq,Wk,Wv,Wo fp16
__device__ __half g_qh  [ROWS*DDIM];
__device__ __half g_kh  [ROWS*DDIM];
__device__ __half g_vth [ROWS*DDIM];     // transposed per head: [(b*HH+h)*DK+d][s]
__device__ __half g_ctxh[ROWS*DDIM];

// ---------------------------------------------------------------------------
// helpers
// ---------------------------------------------------------------------------
__device__ __forceinline__ void mma_f16(float acc[4], const unsigned a[4], const unsigned b[2]) {
    asm volatile(
        "mma.sync.aligned.m16n8k16.row.col.f32.f16.f16.f32 "
        "{%0,%1,%2,%3}, {%4,%5,%6,%7}, {%8,%9}, {%0,%1,%2,%3};"
        : "+f"(acc[0]), "+f"(acc[1]), "+f"(acc[2]), "+f"(acc[3])
        : "r"(a[0]), "r"(a[1]), "r"(a[2]), "r"(a[3]), "r"(b[0]), "r"(b[1]));
}

// FMA-pipe exp via 2^t decomposition, no MUFU. t = x*log2e.
__device__ __forceinline__ float exp_poly_t(float t) {
    t = fmaxf(t, -126.0f);
    const float MAGIC = 12582912.0f;       // 2^23 * 1.5
    float z = t + MAGIC;
    int   i = __float_as_int(z);
    float r = t - (z - MAGIC);             // r in [-0.5, 0.5]
    float p = 0.00133335581f;
    p = fmaf(p, r, 0.00961804886f);
    p = fmaf(p, r, 0.0555041086f);
    p = fmaf(p, r, 0.240226507f);
    p = fmaf(p, r, 0.693147182f);
    p = fmaf(p, r, 1.0f);
    float s = __int_as_float((i - 0x4B400000 + 127) << 23);
    return p * s;
}

__device__ __forceinline__ uint2 f4_to_h4(float4 v) {
    __half2 lo = __floats2half2_rn(v.x, v.y);
    __half2 hi = __floats2half2_rn(v.z, v.w);
    uint2 r;
    r.x = *(unsigned*)&lo;
    r.y = *(unsigned*)&hi;
    return r;
}

__device__ __forceinline__ unsigned smem_u32p(const void* p) {
    return (unsigned)__cvta_generic_to_shared(p);
}
#define CP_ASYNC16(dst, src) asm volatile("cp.async.cg.shared.global [%0], [%1], 16;" :: "r"(dst), "l"(src))
#define CP_COMMIT() asm volatile("cp.async.commit_group;" ::: "memory")
#define CP_WAIT1()  asm volatile("cp.async.wait_group 1;" ::: "memory")
#define CP_WAIT0()  asm volatile("cp.async.wait_group 0;" ::: "memory")

// ---------------------------------------------------------------------------
// LayerNorm -> qn (fp16) + query copy (fp16)
// ---------------------------------------------------------------------------
__global__ __launch_bounds__(256)
void ln_kernel(const float* __restrict__ x, const float* __restrict__ gamma,
               const float* __restrict__ beta,
               __half* __restrict__ qnh, __half* __restrict__ xh)
{
    __shared__ float red[256];
    const int row = blockIdx.x;
    const int tid = threadIdx.x;
    float4 v = ((const float4*)(x + (size_t)row*DDIM))[tid];

    float s = v.x + v.y + v.z + v.w;
    red[tid] = s; __syncthreads();
    #pragma unroll
    for (int o = 128; o > 0; o >>= 1) { if (tid < o) red[tid] += red[tid+o]; __syncthreads(); }
    const float mean = red[0] * (1.0f/DDIM);
    __syncthreads();

    float dx0 = v.x-mean, dx1 = v.y-mean, dx2 = v.z-mean, dx3 = v.w-mean;
    float s2 = dx0*dx0 + dx1*dx1 + dx2*dx2 + dx3*dx3;
    red[tid] = s2; __syncthreads();
    #pragma unroll
    for (int o = 128; o > 0; o >>= 1) { if (tid < o) red[tid] += red[tid+o]; __syncthreads(); }
    const float var = red[0] * (1.0f/DDIM);
    const float rstd = rsqrtf(var + 1e-6f);

    float4 g = ((const float4*)gamma)[tid];
    float4 b = ((const float4*)beta )[tid];
    float4 o4;
    o4.x = dx0*rstd*g.x + b.x;
    o4.y = dx1*rstd*g.y + b.y;
    o4.z = dx2*rstd*g.z + b.z;
    o4.w = dx3*rstd*g.w + b.w;
    *(uint2*)&qnh[(size_t)row*DDIM + tid*4] = f4_to_h4(o4);
    *(uint2*)&xh [(size_t)row*DDIM + tid*4] = f4_to_h4(v);
}

// Convert the 4 weight matrices to fp16: g_wh[z*DDIM*DDIM + ...]
__global__ __launch_bounds__(256)
void cvt_w(const float* __restrict__ W0, const float* __restrict__ W1,
           const float* __restrict__ W2, const float* __restrict__ W3,
           __half* __restrict__ out)
{
    const float* src = (blockIdx.y == 0) ? W0 : (blockIdx.y == 1) ? W1 :
                       (blockIdx.y == 2) ? W2 : W3;
    const size_t idx = ((size_t)blockIdx.x*256 + threadIdx.x) * 4;
    float4 v = *(const float4*)(src + idx);
    *(uint2*)&out[(size_t)blockIdx.y*DDIM*DDIM + idx] = f4_to_h4(v);
}

// ---------------------------------------------------------------------------
// all-fp16 NT GEMM: 64x128 tile, k-step 32, cp.async 3-stage pipeline,
// one barrier per step. fp32 accumulate.
// ---------------------------------------------------------------------------
#define GK 32
#define GSTR 40   // halves; 80B rows (16B-aligned), 20-word stride: conflict-free

__device__ __forceinline__
void gemm_stage(const __half* __restrict__ Ag, const __half* __restrict__ Wg,
                __half* __restrict__ as, __half* __restrict__ bs,
                int k0, int K, int tid)
{
    const int ar = tid >> 2;
    const int ac = (tid & 3) * 8;
    CP_ASYNC16(smem_u32p(as + ar*GSTR + ac), Ag + (size_t)ar*K + k0 + ac);
    CP_ASYNC16(smem_u32p(bs + ar*GSTR + ac), Wg + (size_t)ar*K + k0 + ac);
    CP_ASYNC16(smem_u32p(bs + (ar+64)*GSTR + ac), Wg + (size_t)(ar+64)*K + k0 + ac);
}

__device__ __forceinline__
void gemm_h_body(const __half* __restrict__ A, const __half* __restrict__ W,
                 const float* __restrict__ bias, const float* __restrict__ resid,
                 void* __restrict__ Cout, int N, int K, int mode,
                 __half* As, __half* Bs)   // As: 3*[64*GSTR], Bs: 3*[128*GSTR]
{
    const int tid  = threadIdx.x;
    const int lane = tid & 31;
    const int warp = tid >> 5;
    const int wm   = warp >> 2;
    const int wn   = warp & 3;
    const int gid  = lane >> 2;
    const int tig  = lane & 3;

    const int rowBase = blockIdx.y * 64;
    const int colBase = blockIdx.x * 128;
    const __half* Ag = A + (size_t)rowBase * K;
    const __half* Wg = W + (size_t)colBase * K;

    float acc[2][4][4];
    #pragma unroll
    for (int mt = 0; mt < 2; mt++)
        #pragma unroll
        for (int nt = 0; nt < 4; nt++)
            #pragma unroll
            for (int c = 0; c < 4; c++) acc[mt][nt][c] = 0.0f;

    gemm_stage(Ag, Wg, As, Bs, 0, K, tid);  CP_COMMIT();
    gemm_stage(Ag, Wg, As + 64*GSTR, Bs + 128*GSTR, GK, K, tid);  CP_COMMIT();

    const int NS = K / GK;   // 32
    for (int s = 0; s < NS; s++) {
        if (s == NS-1) { CP_WAIT0(); } else { CP_WAIT1(); }
        __syncthreads();
        if (s + 2 < NS) {
            const int b = (s + 2) % 3;
            gemm_stage(Ag, Wg, As + b*64*GSTR, Bs + b*128*GSTR, (s+2)*GK, K, tid);
            CP_COMMIT();
        }
        const __half* as = As + (s % 3)*64*GSTR;
        const __half* bs = Bs + (s % 3)*128*GSTR;
        #pragma unroll
        for (int sub = 0; sub < 2; sub++) {
            const int ks = sub * 16;
            unsigned afr[2][4];
            #pragma unroll
            for (int mt = 0; mt < 2; mt++) {
                const __half* ap = as + (wm*32 + mt*16)*GSTR + ks;
                afr[mt][0] = *(const unsigned*)&ap[ gid     *GSTR + 2*tig    ];
                afr[mt][1] = *(const unsigned*)&ap[(gid + 8)*GSTR + 2*tig    ];
                afr[mt][2] = *(const unsigned*)&ap[ gid     *GSTR + 2*tig + 8];
                afr[mt][3] = *(const unsigned*)&ap[(gid + 8)*GSTR + 2*tig + 8];
            }
            unsigned bfr[4][2];
            #pragma unroll
            for (int nt = 0; nt < 4; nt++) {
                const __half* bp = bs + (wn*32 + nt*8)*GSTR + ks;
                bfr[nt][0] = *(const unsigned*)&bp[gid*GSTR + 2*tig    ];
                bfr[nt][1] = *(const unsigned*)&bp[gid*GSTR + 2*tig + 8];
            }
            #pragma unroll
            for (int mt = 0; mt < 2; mt++)
                #pragma unroll
                for (int nt = 0; nt < 4; nt++)
                    mma_f16(acc[mt][nt], afr[mt], bfr[nt]);
        }
    }

    #pragma unroll
    for (int nt = 0; nt < 4; nt++) {
        const int col = colBase + wn*32 + nt*8 + tig*2;
        float2 bz = *(const float2*)&bias[col];
        #pragma unroll
        for (int mt = 0; mt < 2; mt++) {
            const int r0 = rowBase + wm*32 + mt*16 + gid;
            const int r1 = r0 + 8;
            float2 v0 = { acc[mt][nt][0] + bz.x, acc[mt][nt][1] + bz.y };
            float2 v1 = { acc[mt][nt][2] + bz.x, acc[mt][nt][3] + bz.y };
            if (mode == 0) {
                if (resid) {
                    float2 q0 = *(const float2*)&resid[(size_t)r0*N + col];
                    float2 q1 = *(const float2*)&resid[(size_t)r1*N + col];
                    v0.x += q0.x; v0.y += q0.y;
                    v1.x += q1.x; v1.y += q1.y;
                }
                float* C = (float*)Cout;
                *(float2*)&C[(size_t)r0*N + col] = v0;
                *(float2*)&C[(size_t)r1*N + col] = v1;
            } else if (mode == 1) {
                __half* C = (__half*)Cout;
                *(__half2*)&C[(size_t)r0*N + col] = __floats2half2_rn(v0.x, v0.y);
                *(__half2*)&C[(size_t)r1*N + col] = __floats2half2_rn(v1.x, v1.y);
            } else {
                __half* C = (__half*)Cout;
                const int h = col >> 6;
                const int d = col & 63;
                {
                    const int b = r0 >> 10, s2 = r0 & 1023;
                    const size_t base = ((size_t)(b*HH + h)*DK + d)*LLE + s2;
                    C[base      ] = __float2half_rn(v0.x);
                    C[base + LLE] = __float2half_rn(v0.y);
                }
                {
                    const int b = r1 >> 10, s2 = r1 & 1023;
                    const size_t base = ((size_t)(b*HH + h)*DK + d)*LLE + s2;
                    C[base      ] = __float2half_rn(v1.x);
                    C[base + LLE] = __float2half_rn(v1.y);
                }
            }
        }
    }
}

__global__ __launch_bounds__(256)
void qkv_gemm(const __half* __restrict__ qnh, const __half* __restrict__ xh,
              const __half* __restrict__ Wh,
              const float* __restrict__ bq, const float* __restrict__ bk, const float* __restrict__ bv,
              __half* __restrict__ Qh, __half* __restrict__ Kh, __half* __restrict__ Vth)
{
    __shared__ __half As[3*64*GSTR];
    __shared__ __half Bs[3*128*GSTR];
    const int z = blockIdx.z;
    const __half* A = (z == 0) ? qnh : xh;
    const __half* W = Wh + (size_t)z*DDIM*DDIM;
    const float* b  = (z == 0) ? bq : (z == 1) ? bk : bv;
    void* C         = (z == 0) ? (void*)Qh : (z == 1) ? (void*)Kh : (void*)Vth;
    const int mode  = (z == 2) ? 2 : 1;
    gemm_h_body(A, W, b, nullptr, C, DDIM, DDIM, mode, As, Bs);
}

__global__ __launch_bounds__(256)
void out_gemm(const __half* __restrict__ A, const __half* __restrict__ Wh,
              const float* __restrict__ bias, const float* __restrict__ resid,
              float* __restrict__ C)
{
    __shared__ __half As[3*64*GSTR];
    __shared__ __half Bs[3*128*GSTR];
    gemm_h_body(A, Wh, bias, resid, C, DDIM, DDIM, 0, As, Bs);
}

// ---------------------------------------------------------------------------
// Fused attention, fp16, QT=32, 512 threads, 2 CTAs/SM.
// Unified 32-stage cp.async pipeline (stages 0-15: K tiles, 16-31: V tiles),
// 3 buffers, ONE barrier per tile. Max-free softmax in QK epilogue; __stcs attn.
// 16 warps: wq = w&1 (16-row q slab), wn = w>>1 (8-col s/d slab).
// ---------------------------------------------------------------------------
#define QT 32
#define ST2 64
#define NTIL (LLE/ST2)               // 16
#define S_STRH 1048
#define KV_STRH 72
#define KVB (64*KV_STRH)             // 4608 halves per buffer
// halves offsets
#define OFF_KV_H 33536               // 32*1048
#define OFF_Q_H  47360               // +3*4608
// byte offsets
#define OFF_RS_B 99328               // (47360+32*72)*2
#define OFF_INV_B 100352             // +32*8*4
#define SM_BYTES_A 100480            // +32*4

__device__ __forceinline__ void stage64h_512(const __half* __restrict__ g,
                                             __half* __restrict__ s, int tid)
{
    const int row = tid >> 3;
    const int col = (tid & 7) * 8;
    CP_ASYNC16(smem_u32p(s + row*KV_STRH + col), g + (size_t)row*1024 + col);
}

__global__ void __launch_bounds__(512, 2)
attn_fused(const __half* __restrict__ Qh, const __half* __restrict__ Kh,
           const __half* __restrict__ Vth,
           const float* __restrict__ pos_bias, const float* __restrict__ postag,
           const float* __restrict__ lex, const int* __restrict__ mask,
           float* __restrict__ attn, __half* __restrict__ ctxh)
{
    extern __shared__ __align__(16) char smraw[];
    __half* S_h  = (__half*)smraw;               // [QT][S_STRH]
    __half* KV   = (__half*)smraw + OFF_KV_H;    // 3 buffers [64][72]
    __half* Qs   = (__half*)smraw + OFF_Q_H;     // [32][72]
    float*  rs   = (float*)(smraw + OFF_RS_B);   // [32][8]
    float*  invS = (float*)(smraw + OFF_INV_B);  // [32]

    const int tid  = threadIdx.x;
    const int lane = tid & 31;
    const int w    = tid >> 5;           // 0..15
    const int wq   = w & 1;              // q slab (16 rows)
    const int wn   = w >> 1;             // 0..7 : col slab (8)
    const int gid  = lane >> 2;
    const int tig  = lane & 3;
    const int qBase = blockIdx.x * QT;
    const int bh = blockIdx.y;
    const int b = bh >> 4, h = bh & 15;

    const __half* Kbase = Kh  + (size_t)(b*LLE)*DDIM + h*DK;
    const __half* Vbase = Vth + (size_t)bh*DK*LLE;

    // prologue: group0 = Q (32x64) + K0, group1 = K1
    if (tid < 256) {
        const int row = tid >> 3;
        const int col = (tid & 7) * 8;
        CP_ASYNC16(smem_u32p(Qs + row*KV_STRH + col),
                   Qh + (size_t)(b*LLE + qBase + row)*DDIM + h*DK + col);
    }
    stage64h_512(Kbase, KV, tid);
    CP_COMMIT();
    stage64h_512(Kbase + (size_t)ST2*DDIM, KV + KVB, tid);
    CP_COMMIT();

    const int r0g = qBase + wq*16 + gid;
    const int r1g = r0g + 8;
    const float* pbRow0 = &pos_bias[((size_t)h*LLE + r0g)*LLE];
    const float* pbRow1 = &pos_bias[((size_t)h*LLE + r1g)*LLE];
    const float* ptRow0 = &postag  [((size_t)bh*LLE + r0g)*LLE];
    const float* ptRow1 = &postag  [((size_t)bh*LLE + r1g)*LLE];
    const int sgBase = wn*8 + tig*2;

    unsigned qa[4][4];
    float sum0 = 0.0f, sum1 = 0.0f;
    const float LOG2E = 1.4426950408889634f;

    // ---- QK phase ----
    for (int t = 0; t < NTIL; t++) {
        const int sg = t*ST2 + sgBase;
        // issue bias loads before the wait; consumed after the MMA
        const float2 pb0 = *(const float2*)&pbRow0[sg];
        const float2 pb1 = *(const float2*)&pbRow1[sg];
        const float2 pt0 = *(const float2*)&ptRow0[sg];
        const float2 pt1 = *(const float2*)&ptRow1[sg];
        const float2 lx  = *(const float2*)&lex [b*LLE + sg];
        const int2   mk  = *(const int2 *)&mask[b*LLE + sg];

        CP_WAIT1();
        __syncthreads();

        {   // stage pipeline slot s = t+2 (K tile if <16, else V tile)
            const int s = t + 2;
            const __half* gsrc = (s < 16) ? (Kbase + (size_t)s*ST2*DDIM)
                                          : (Vbase + (size_t)(s - 16)*ST2);
            stage64h_512(gsrc, KV + (s % 3)*KVB, tid);
            CP_COMMIT();
        }

        if (t == 0) {
            #pragma unroll
            for (int ks = 0; ks < 4; ks++) {
                qa[ks][0] = *(const unsigned*)&Qs[(wq*16 + gid    )*KV_STRH + ks*16 + 2*tig    ];
                qa[ks][1] = *(const unsigned*)&Qs[(wq*16 + gid + 8)*KV_STRH + ks*16 + 2*tig    ];
                qa[ks][2] = *(const unsigned*)&Qs[(wq*16 + gid    )*KV_STRH + ks*16 + 2*tig + 8];
                qa[ks][3] = *(const unsigned*)&Qs[(wq*16 + gid + 8)*KV_STRH + ks*16 + 2*tig + 8];
            }
        }

        const __half* Kb = KV + (t % 3)*KVB;
        float acc[4] = {0.0f, 0.0f, 0.0f, 0.0f};
        #pragma unroll
        for (int ks = 0; ks < 4; ks++) {
            unsigned bf[2];
            bf[0] = *(const unsigned*)&Kb[(wn*8 + gid)*KV_STRH + ks*16 + 2*tig    ];
            bf[1] = *(const unsigned*)&Kb[(wn*8 + gid)*KV_STRH + ks*16 + 2*tig + 8];
            mma_f16(acc, qa[ks], bf);
        }

        // epilogue: logits -> exp (max-free, masked -> 0) -> S (fp16)
        {
            float l0x = acc[0]*0.125f + pb0.x + pt0.x + lx.x;
            float l0y = acc[1]*0.125f + pb0.y + pt0.y + lx.y;
            float l1x = acc[2]*0.125f + pb1.x + pt1.x + lx.x;
            float l1y = acc[3]*0.125f + pb1.y + pt1.y + lx.y;
            float p0x = (mk.x == 0) ? 0.0f : __expf(l0x);
            float p0y = (mk.y == 0) ? 0.0f : exp_poly_t(l0y * LOG2E);
            float p1x = (mk.x == 0) ? 0.0f : __expf(l1x);
            float p1y = (mk.y == 0) ? 0.0f : exp_poly_t(l1y * LOG2E);
            sum0 += p0x + p0y;
            sum1 += p1x + p1y;
            *(__half2*)&S_h[(wq*16 + gid    )*S_STRH + sg] = __floats2half2_rn(p0x, p0y);
            *(__half2*)&S_h[(wq*16 + gid + 8)*S_STRH + sg] = __floats2half2_rn(p1x, p1y);
        }
    }

    // ---- rowsum reduction -> inv[32] (V tiles 0/1 already in flight) ----
    {
        float a = sum0, c = sum1;
        a += __shfl_xor_sync(0xffffffffu, a, 1);
        a += __shfl_xor_sync(0xffffffffu, a, 2);
        c += __shfl_xor_sync(0xffffffffu, c, 1);
        c += __shfl_xor_sync(0xffffffffu, c, 2);
        if (tig == 0) {
            rs[(wq*16 + gid    )*8 + wn] = a;
            rs[(wq*16 + gid + 8)*8 + wn] = c;
        }
    }
    __syncthreads();
    if (tid < 32) {
        float t = 0.0f;
        #pragma unroll
        for (int i = 0; i < 8; i++) t += rs[tid*8 + i];
        invS[tid] = 1.0f / t;
    }
    __syncthreads();

    // ---- attn sweep: attn = S * inv, streaming stores ----
    {
        const int row = tid >> 4;         // 0..31
        const float inv = invS[row];
        float* arow = &attn[((size_t)bh*LLE + qBase + row)*LLE];
        #pragma unroll
        for (int j = 0; j < 16; j++) {
            const int c4 = (tid & 15) + j*16;
            __half2 h0 = *(const __half2*)&S_h[row*S_STRH + c4*4    ];
            __half2 h1 = *(const __half2*)&S_h[row*S_STRH + c4*4 + 2];
            float2 f0 = __half22float2(h0);
            float2 f1 = __half22float2(h1);
            float4 p = {f0.x*inv, f0.y*inv, f1.x*inv, f1.y*inv};
            __stcs((float4*)&arow[c4*4], p);
        }
    }

    // ---- AV phase (pipeline stages 16..31) ----
    float av[4] = {0.0f, 0.0f, 0.0f, 0.0f};
    for (int t = 0; t < NTIL; t++) {
        if (t == NTIL-1) { CP_WAIT0(); } else { CP_WAIT1(); }
        __syncthreads();
        if (t + 2 < NTIL) {
            const int s = 16 + t + 2;
            stage64h_512(Vbase + (size_t)(t + 2)*ST2, KV + (s % 3)*KVB, tid);
            CP_COMMIT();
        }

        const __half* Vb = KV + ((16 + t) % 3)*KVB;
        #pragma unroll
        for (int ks = 0; ks < 4; ks++) {
            const int kk = t*ST2 + ks*16;
            unsigned af[4];
            af[0] = *(const unsigned*)&S_h[(wq*16 + gid    )*S_STRH + kk + 2*tig    ];
            af[1] = *(const unsigned*)&S_h[(wq*16 + gid + 8)*S_STRH + kk + 2*tig    ];
            af[2] = *(const unsigned*)&S_h[(wq*16 + gid    )*S_STRH + kk + 2*tig + 8];
            af[3] = *(const unsigned*)&S_h[(wq*16 + gid + 8)*S_STRH + kk + 2*tig + 8];
            unsigned bf[2];
            bf[0] = *(const unsigned*)&Vb[(wn*8 + gid)*KV_STRH + ks*16 + 2*tig    ];
            bf[1] = *(const unsigned*)&Vb[(wn*8 + gid)*KV_STRH + ks*16 + 2*tig + 8];
            mma_f16(av, af, bf);
        }
    }

    // write ctx (fp16, scaled by inv)
    {
        const float inv0 = invS[wq*16 + gid];
        const float inv1 = invS[wq*16 + gid + 8];
        const int cc = h*DK + wn*8 + tig*2;
        const int r0 = b*LLE + qBase + wq*16 + gid;
        *(__half2*)&ctxh[(size_t)r0*DDIM + cc]     = __floats2half2_rn(av[0]*inv0, av[1]*inv0);
        *(__half2*)&ctxh[(size_t)(r0+8)*DDIM + cc] = __floats2half2_rn(av[2]*inv1, av[3]*inv1);
    }
}

// ---------------------------------------------------------------------------
extern "C" void kernel_launch(void* const* d_in, const int* in_sizes, int n_in,
                              void* d_out, int out_size)
{
    const float* query  = (const float*)d_in[0];
    const float* pos_b  = (const float*)d_in[1];
    const float* postag = (const float*)d_in[2];
    const float* lex    = (const float*)d_in[3];
    const int*   mask   = (const int*  )d_in[4];
    const float* Wq = (const float*)d_in[5];
    const float* bq = (const float*)d_in[6];
    const float* Wk = (const float*)d_in[7];
    const float* bk = (const float*)d_in[8];
    const float* Wv = (const float*)d_in[9];
    const float* bv = (const float*)d_in[10];
    const float* Wo = (const float*)d_in[11];
    const float* bo = (const float*)d_in[12];
    const float* gamma = (const float*)d_in[13];
    const float* beta  = (const float*)d_in[14];

    float* out  = (float*)d_out;             // (B,L,D)
    float* attn = (float*)d_out + OUT_ELEMS; // (B,H,L,L)

    __half* qnh  = nullptr; cudaGetSymbolAddress((void**)&qnh,  g_qnh);
    __half* xh   = nullptr; cudaGetSymbolAddress((void**)&xh,   g_xh);
    __half* Wh   = nullptr; cudaGetSymbolAddress((void**)&Wh,   g_wh);
    __half* Qh   = nullptr; cudaGetSymbolAddress((void**)&Qh,   g_qh);
    __half* Kh   = nullptr; cudaGetSymbolAddress((void**)&Kh,   g_kh);
    __half* Vth  = nullptr; cudaGetSymbolAddress((void**)&Vth,  g_vth);
    __half* ctxh = nullptr; cudaGetSymbolAddress((void**)&ctxh, g_ctxh);

    cudaFuncSetAttribute(attn_fused, cudaFuncAttributeMaxDynamicSharedMemorySize, SM_BYTES_A);

    // 1) pre-LN (emit qn fp16 + query fp16) and weight conversion
    ln_kernel<<<ROWS, 256>>>(query, gamma, beta, qnh, xh);
    cvt_w<<<dim3(1024, 4), 256>>>(Wq, Wk, Wv, Wo, Wh);

    // 2) Q/K/V projections (768 CTAs), fp16 in, fp16 out (V transposed)
    dim3 qkvGrid(DDIM/128, ROWS/64, 3);
    qkv_gemm<<<qkvGrid, 256>>>(qnh, xh, Wh, bq, bk, bv, Qh, Kh, Vth);

    // 3) fused logits + softmax + AV
    dim3 aGrid(LLE/QT, BB*HH);
    attn_fused<<<aGrid, 512, SM_BYTES_A>>>(Qh, Kh, Vth, pos_b, postag, lex, mask, attn, ctxh);

    // 4) out = ctx @ Wo^T + bo + residual(query)
    dim3 oGrid(DDIM/128, ROWS/64);
    out_gemm<<<oGrid, 256>>>(ctxh, Wh + (size_t)3*DDIM*DDIM, bo, query, out);
}

// round 17
// speedup vs baseline: 1.2552x; 1.2552x over previous
#include <cuda_runtime.h>
#include <cuda_fp16.h>
#include <math.h>

#define BB 2
#define LLE 1024
#define DDIM 1024
#define HH 16
#define DK 64
#define ROWS (BB*LLE)            // 2048
#define OUT_ELEMS (BB*LLE*DDIM)  // 2,097,152

// Scratch (allocation-free rule: __device__ globals)
__device__ __half g_qnh [ROWS*DDIM];     // LN(query) fp16
__device__ __half g_xh  [ROWS*DDIM];     // query fp16
__device__ __half g_wh  [4*DDIM*DDIM];   // Wq,Wk,Wv,Wo fp16
__device__ __half g_qh  [ROWS*DDIM];
__device__ __half g_kh  [ROWS*DDIM];
__device__ __half g_vth [ROWS*DDIM];     // transposed per head: [(b*HH+h)*DK+d][s]
__device__ __half g_ctxh[ROWS*DDIM];

// ---------------------------------------------------------------------------
// helpers
// ---------------------------------------------------------------------------
__device__ __forceinline__ void mma_f16(float acc[4], const unsigned a[4], const unsigned b[2]) {
    asm volatile(
        "mma.sync.aligned.m16n8k16.row.col.f32.f16.f16.f32 "
        "{%0,%1,%2,%3}, {%4,%5,%6,%7}, {%8,%9}, {%0,%1,%2,%3};"
        : "+f"(acc[0]), "+f"(acc[1]), "+f"(acc[2]), "+f"(acc[3])
        : "r"(a[0]), "r"(a[1]), "r"(a[2]), "r"(a[3]), "r"(b[0]), "r"(b[1]));
}

// FMA-pipe exp via 2^t decomposition, no MUFU. t = x*log2e.
__device__ __forceinline__ float exp_poly_t(float t) {
    t = fmaxf(t, -126.0f);
    const float MAGIC = 12582912.0f;       // 2^23 * 1.5
    float z = t + MAGIC;
    int   i = __float_as_int(z);
    float r = t - (z - MAGIC);             // r in [-0.5, 0.5]
    float p = 0.00133335581f;
    p = fmaf(p, r, 0.00961804886f);
    p = fmaf(p, r, 0.0555041086f);
    p = fmaf(p, r, 0.240226507f);
    p = fmaf(p, r, 0.693147182f);
    p = fmaf(p, r, 1.0f);
    float s = __int_as_float((i - 0x4B400000 + 127) << 23);
    return p * s;
}

__device__ __forceinline__ uint2 f4_to_h4(float4 v) {
    __half2 lo = __floats2half2_rn(v.x, v.y);
    __half2 hi = __floats2half2_rn(v.z, v.w);
    uint2 r;
    r.x = *(unsigned*)&lo;
    r.y = *(unsigned*)&hi;
    return r;
}

__device__ __forceinline__ unsigned smem_u32p(const void* p) {
    return (unsigned)__cvta_generic_to_shared(p);
}
#define CP_ASYNC16(dst, src) asm volatile("cp.async.cg.shared.global [%0], [%1], 16;" :: "r"(dst), "l"(src))
#define CP_COMMIT() asm volatile("cp.async.commit_group;" ::: "memory")
#define CP_WAIT1()  asm volatile("cp.async.wait_group 1;" ::: "memory")
#define CP_WAIT0()  asm volatile("cp.async.wait_group 0;" ::: "memory")

// ---------------------------------------------------------------------------
// LayerNorm -> qn (fp16) + query copy (fp16)
// ---------------------------------------------------------------------------
__global__ __launch_bounds__(256)
void ln_kernel(const float* __restrict__ x, const float* __restrict__ gamma,
               const float* __restrict__ beta,
               __half* __restrict__ qnh, __half* __restrict__ xh)
{
    __shared__ float red[256];
    const int row = blockIdx.x;
    const int tid = threadIdx.x;
    float4 v = ((const float4*)(x + (size_t)row*DDIM))[tid];

    float s = v.x + v.y + v.z + v.w;
    red[tid] = s; __syncthreads();
    #pragma unroll
    for (int o = 128; o > 0; o >>= 1) { if (tid < o) red[tid] += red[tid+o]; __syncthreads(); }
    const float mean = red[0] * (1.0f/DDIM);
    __syncthreads();

    float dx0 = v.x-mean, dx1 = v.y-mean, dx2 = v.z-mean, dx3 = v.w-mean;
    float s2 = dx0*dx0 + dx1*dx1 + dx2*dx2 + dx3*dx3;
    red[tid] = s2; __syncthreads();
    #pragma unroll
    for (int o = 128; o > 0; o >>= 1) { if (tid < o) red[tid] += red[tid+o]; __syncthreads(); }
    const float var = red[0] * (1.0f/DDIM);
    const float rstd = rsqrtf(var + 1e-6f);

    float4 g = ((const float4*)gamma)[tid];
    float4 b = ((const float4*)beta )[tid];
    float4 o4;
    o4.x = dx0*rstd*g.x + b.x;
    o4.y = dx1*rstd*g.y + b.y;
    o4.z = dx2*rstd*g.z + b.z;
    o4.w = dx3*rstd*g.w + b.w;
    *(uint2*)&qnh[(size_t)row*DDIM + tid*4] = f4_to_h4(o4);
    *(uint2*)&xh [(size_t)row*DDIM + tid*4] = f4_to_h4(v);
}

// Convert the 4 weight matrices to fp16: g_wh[z*DDIM*DDIM + ...]
__global__ __launch_bounds__(256)
void cvt_w(const float* __restrict__ W0, const float* __restrict__ W1,
           const float* __restrict__ W2, const float* __restrict__ W3,
           __half* __restrict__ out)
{
    const float* src = (blockIdx.y == 0) ? W0 : (blockIdx.y == 1) ? W1 :
                       (blockIdx.y == 2) ? W2 : W3;
    const size_t idx = ((size_t)blockIdx.x*256 + threadIdx.x) * 4;
    float4 v = *(const float4*)(src + idx);
    *(uint2*)&out[(size_t)blockIdx.y*DDIM*DDIM + idx] = f4_to_h4(v);
}

// ---------------------------------------------------------------------------
// all-fp16 NT GEMM: 64x128 tile, k-step 32, cp.async 3-stage pipeline,
// one barrier per step. fp32 accumulate. (unchanged from R15)
// ---------------------------------------------------------------------------
#define GK 32
#define GSTR 40   // halves; 80B rows (16B-aligned), 20-word stride: conflict-free

__device__ __forceinline__
void gemm_stage(const __half* __restrict__ Ag, const __half* __restrict__ Wg,
                __half* __restrict__ as, __half* __restrict__ bs,
                int k0, int K, int tid)
{
    const int ar = tid >> 2;
    const int ac = (tid & 3) * 8;
    CP_ASYNC16(smem_u32p(as + ar*GSTR + ac), Ag + (size_t)ar*K + k0 + ac);
    CP_ASYNC16(smem_u32p(bs + ar*GSTR + ac), Wg + (size_t)ar*K + k0 + ac);
    CP_ASYNC16(smem_u32p(bs + (ar+64)*GSTR + ac), Wg + (size_t)(ar+64)*K + k0 + ac);
}

__device__ __forceinline__
void gemm_h_body(const __half* __restrict__ A, const __half* __restrict__ W,
                 const float* __restrict__ bias, const float* __restrict__ resid,
                 void* __restrict__ Cout, int N, int K, int mode,
                 __half* As, __half* Bs)   // As: 3*[64*GSTR], Bs: 3*[128*GSTR]
{
    const int tid  = threadIdx.x;
    const int lane = tid & 31;
    const int warp = tid >> 5;
    const int wm   = warp >> 2;
    const int wn   = warp & 3;
    const int gid  = lane >> 2;
    const int tig  = lane & 3;

    const int rowBase = blockIdx.y * 64;
    const int colBase = blockIdx.x * 128;
    const __half* Ag = A + (size_t)rowBase * K;
    const __half* Wg = W + (size_t)colBase * K;

    float acc[2][4][4];
    #pragma unroll
    for (int mt = 0; mt < 2; mt++)
        #pragma unroll
        for (int nt = 0; nt < 4; nt++)
            #pragma unroll
            for (int c = 0; c < 4; c++) acc[mt][nt][c] = 0.0f;

    gemm_stage(Ag, Wg, As, Bs, 0, K, tid);  CP_COMMIT();
    gemm_stage(Ag, Wg, As + 64*GSTR, Bs + 128*GSTR, GK, K, tid);  CP_COMMIT();

    const int NS = K / GK;   // 32
    for (int s = 0; s < NS; s++) {
        if (s == NS-1) { CP_WAIT0(); } else { CP_WAIT1(); }
        __syncthreads();
        if (s + 2 < NS) {
            const int b = (s + 2) % 3;
            gemm_stage(Ag, Wg, As + b*64*GSTR, Bs + b*128*GSTR, (s+2)*GK, K, tid);
            CP_COMMIT();
        }
        const __half* as = As + (s % 3)*64*GSTR;
        const __half* bs = Bs + (s % 3)*128*GSTR;
        #pragma unroll
        for (int sub = 0; sub < 2; sub++) {
            const int ks = sub * 16;
            unsigned afr[2][4];
            #pragma unroll
            for (int mt = 0; mt < 2; mt++) {
                const __half* ap = as + (wm*32 + mt*16)*GSTR + ks;
                afr[mt][0] = *(const unsigned*)&ap[ gid     *GSTR + 2*tig    ];
                afr[mt][1] = *(const unsigned*)&ap[(gid + 8)*GSTR + 2*tig    ];
                afr[mt][2] = *(const unsigned*)&ap[ gid     *GSTR + 2*tig + 8];
                afr[mt][3] = *(const unsigned*)&ap[(gid + 8)*GSTR + 2*tig + 8];
            }
            unsigned bfr[4][2];
            #pragma unroll
            for (int nt = 0; nt < 4; nt++) {
                const __half* bp = bs + (wn*32 + nt*8)*GSTR + ks;
                bfr[nt][0] = *(const unsigned*)&bp[gid*GSTR + 2*tig    ];
                bfr[nt][1] = *(const unsigned*)&bp[gid*GSTR + 2*tig + 8];
            }
            #pragma unroll
            for (int mt = 0; mt < 2; mt++)
                #pragma unroll
                for (int nt = 0; nt < 4; nt++)
                    mma_f16(acc[mt][nt], afr[mt], bfr[nt]);
        }
    }

    #pragma unroll
    for (int nt = 0; nt < 4; nt++) {
        const int col = colBase + wn*32 + nt*8 + tig*2;
        float2 bz = *(const float2*)&bias[col];
        #pragma unroll
        for (int mt = 0; mt < 2; mt++) {
            const int r0 = rowBase + wm*32 + mt*16 + gid;
            const int r1 = r0 + 8;
            float2 v0 = { acc[mt][nt][0] + bz.x, acc[mt][nt][1] + bz.y };
            float2 v1 = { acc[mt][nt][2] + bz.x, acc[mt][nt][3] + bz.y };
            if (mode == 0) {
                if (resid) {
                    float2 q0 = *(const float2*)&resid[(size_t)r0*N + col];
                    float2 q1 = *(const float2*)&resid[(size_t)r1*N + col];
                    v0.x += q0.x; v0.y += q0.y;
                    v1.x += q1.x; v1.y += q1.y;
                }
                float* C = (float*)Cout;
                *(float2*)&C[(size_t)r0*N + col] = v0;
                *(float2*)&C[(size_t)r1*N + col] = v1;
            } else if (mode == 1) {
                __half* C = (__half*)Cout;
                *(__half2*)&C[(size_t)r0*N + col] = __floats2half2_rn(v0.x, v0.y);
                *(__half2*)&C[(size_t)r1*N + col] = __floats2half2_rn(v1.x, v1.y);
            } else {
                __half* C = (__half*)Cout;
                const int h = col >> 6;
                const int d = col & 63;
                {
                    const int b = r0 >> 10, s2 = r0 & 1023;
                    const size_t base = ((size_t)(b*HH + h)*DK + d)*LLE + s2;
                    C[base      ] = __float2half_rn(v0.x);
                    C[base + LLE] = __float2half_rn(v0.y);
                }
                {
                    const int b = r1 >> 10, s2 = r1 & 1023;
                    const size_t base = ((size_t)(b*HH + h)*DK + d)*LLE + s2;
                    C[base      ] = __float2half_rn(v1.x);
                    C[base + LLE] = __float2half_rn(v1.y);
                }
            }
        }
    }
}

__global__ __launch_bounds__(256)
void qkv_gemm(const __half* __restrict__ qnh, const __half* __restrict__ xh,
              const __half* __restrict__ Wh,
              const float* __restrict__ bq, const float* __restrict__ bk, const float* __restrict__ bv,
              __half* __restrict__ Qh, __half* __restrict__ Kh, __half* __restrict__ Vth)
{
    __shared__ __half As[3*64*GSTR];
    __shared__ __half Bs[3*128*GSTR];
    const int z = blockIdx.z;
    const __half* A = (z == 0) ? qnh : xh;
    const __half* W = Wh + (size_t)z*DDIM*DDIM;
    const float* b  = (z == 0) ? bq : (z == 1) ? bk : bv;
    void* C         = (z == 0) ? (void*)Qh : (z == 1) ? (void*)Kh : (void*)Vth;
    const int mode  = (z == 2) ? 2 : 1;
    gemm_h_body(A, W, b, nullptr, C, DDIM, DDIM, mode, As, Bs);
}

__global__ __launch_bounds__(256)
void out_gemm(const __half* __restrict__ A, const __half* __restrict__ Wh,
              const float* __restrict__ bias, const float* __restrict__ resid,
              float* __restrict__ C)
{
    __shared__ __half As[3*64*GSTR];
    __shared__ __half Bs[3*128*GSTR];
    gemm_h_body(A, Wh, bias, resid, C, DDIM, DDIM, 0, As, Bs);
}

// ---------------------------------------------------------------------------
// Fused attention, fp16, QT=16, 256 threads, 3 CTAs/SM.
// BARRIER-FREE tiles: K/V/Q fragments loaded directly from gmem into
// registers (no cross-warp sharing exists), register-double-buffered one tile
// ahead. Smem holds only S + reduction scratch. 3 barriers total.
// ---------------------------------------------------------------------------
#define QT 16
#define ST2 64
#define NTIL (LLE/ST2)               // 16
#define S_STRH 1048
// byte offsets
#define OFF_RS_B 33536               // 16*1048*2
#define OFF_INV_B 34048
#define SM_BYTES_A 34112

__global__ void __launch_bounds__(256, 3)
attn_fused(const __half* __restrict__ Qh, const __half* __restrict__ Kh,
           const __half* __restrict__ Vth,
           const float* __restrict__ pos_bias, const float* __restrict__ postag,
           const float* __restrict__ lex, const int* __restrict__ mask,
           float* __restrict__ attn, __half* __restrict__ ctxh)
{
    extern __shared__ __align__(16) char smraw[];
    __half* S_h  = (__half*)smraw;               // [QT][S_STRH]
    float*  rs   = (float*)(smraw + OFF_RS_B);   // [16][8]
    float*  invS = (float*)(smraw + OFF_INV_B);  // [16]

    const int tid  = threadIdx.x;
    const int lane = tid & 31;
    const int w    = tid >> 5;
    const int gid  = lane >> 2;
    const int tig  = lane & 3;
    const int qBase = blockIdx.x * QT;
    const int bh = blockIdx.y;
    const int b = bh >> 4, h = bh & 15;

    // ---- Q fragments: direct LDG (16 x 32b) ----
    unsigned qa[4][4];
    {
        const __half* Qrow0 = Qh + (size_t)(b*LLE + qBase + gid    )*DDIM + h*DK;
        const __half* Qrow1 = Qh + (size_t)(b*LLE + qBase + gid + 8)*DDIM + h*DK;
        #pragma unroll
        for (int ks = 0; ks < 4; ks++) {
            qa[ks][0] = *(const unsigned*)&Qrow0[ks*16 + 2*tig    ];
            qa[ks][1] = *(const unsigned*)&Qrow1[ks*16 + 2*tig    ];
            qa[ks][2] = *(const unsigned*)&Qrow0[ks*16 + 2*tig + 8];
            qa[ks][3] = *(const unsigned*)&Qrow1[ks*16 + 2*tig + 8];
        }
    }

    // K row for this thread: s = t*64 + w*8 + gid
    const __half* Krow = Kh + (size_t)(b*LLE + w*8 + gid)*DDIM + h*DK;
    const int r0g = qBase + gid;
    const int r1g = r0g + 8;
    const float* pbRow0 = &pos_bias[((size_t)h*LLE + r0g)*LLE];
    const float* pbRow1 = &pos_bias[((size_t)h*LLE + r1g)*LLE];
    const float* ptRow0 = &postag  [((size_t)bh*LLE + r0g)*LLE];
    const float* ptRow1 = &postag  [((size_t)bh*LLE + r1g)*LLE];
    const int sgBase = w*8 + tig*2;

    float sum0 = 0.0f, sum1 = 0.0f;
    const float LOG2E = 1.4426950408889634f;

    // prefetch K fragments for tile 0
    unsigned kf[8];
    #pragma unroll
    for (int ks = 0; ks < 4; ks++) {
        kf[ks*2    ] = *(const unsigned*)&Krow[ks*16 + 2*tig    ];
        kf[ks*2 + 1] = *(const unsigned*)&Krow[ks*16 + 2*tig + 8];
    }

    // ---- QK phase: no barriers ----
    for (int t = 0; t < NTIL; t++) {
        const int sg = t*ST2 + sgBase;
        // prefetch next K tile fragments
        unsigned kn[8];
        if (t + 1 < NTIL) {
            const __half* Kn = Krow + (size_t)(t + 1)*ST2*DDIM;
            #pragma unroll
            for (int ks = 0; ks < 4; ks++) {
                kn[ks*2    ] = *(const unsigned*)&Kn[ks*16 + 2*tig    ];
                kn[ks*2 + 1] = *(const unsigned*)&Kn[ks*16 + 2*tig + 8];
            }
        }
        // bias operands (hidden under MMA)
        const float2 pb0 = *(const float2*)&pbRow0[sg];
        const float2 pb1 = *(const float2*)&pbRow1[sg];
        const float2 pt0 = *(const float2*)&ptRow0[sg];
        const float2 pt1 = *(const float2*)&ptRow1[sg];
        const float2 lx  = *(const float2*)&lex [b*LLE + sg];
        const int2   mk  = *(const int2 *)&mask[b*LLE + sg];

        float acc[4] = {0.0f, 0.0f, 0.0f, 0.0f};
        #pragma unroll
        for (int ks = 0; ks < 4; ks++)
            mma_f16(acc, qa[ks], &kf[ks*2]);

        // epilogue: logits -> exp (max-free, masked -> 0) -> S (fp16)
        {
            float l0x = acc[0]*0.125f + pb0.x + pt0.x + lx.x;
            float l0y = acc[1]*0.125f + pb0.y + pt0.y + lx.y;
            float l1x = acc[2]*0.125f + pb1.x + pt1.x + lx.x;
            float l1y = acc[3]*0.125f + pb1.y + pt1.y + lx.y;
            float p0x = (mk.x == 0) ? 0.0f : __expf(l0x);
            float p0y = (mk.y == 0) ? 0.0f : exp_poly_t(l0y * LOG2E);
            float p1x = (mk.x == 0) ? 0.0f : __expf(l1x);
            float p1y = (mk.y == 0) ? 0.0f : exp_poly_t(l1y * LOG2E);
            sum0 += p0x + p0y;
            sum1 += p1x + p1y;
            *(__half2*)&S_h[ gid     *S_STRH + sg] = __floats2half2_rn(p0x, p0y);
            *(__half2*)&S_h[(gid + 8)*S_STRH + sg] = __floats2half2_rn(p1x, p1y);
        }
        #pragma unroll
        for (int i = 0; i < 8; i++) kf[i] = kn[i];
    }

    // ---- rowsum reduction -> inv[16] ----
    {
        float a = sum0, c = sum1;
        a += __shfl_xor_sync(0xffffffffu, a, 1);
        a += __shfl_xor_sync(0xffffffffu, a, 2);
        c += __shfl_xor_sync(0xffffffffu, c, 1);
        c += __shfl_xor_sync(0xffffffffu, c, 2);
        if (tig == 0) {
            rs[ gid     *8 + w] = a;
            rs[(gid + 8)*8 + w] = c;
        }
    }
    __syncthreads();
    if (tid < 16) {
        float t = 0.0f;
        #pragma unroll
        for (int i = 0; i < 8; i++) t += rs[tid*8 + i];
        invS[tid] = 1.0f / t;
    }
    __syncthreads();

    // ---- attn sweep: attn = S * inv, streaming stores ----
    {
        const int row = tid >> 4;
        const float inv = invS[row];
        float* arow = &attn[((size_t)bh*LLE + qBase + row)*LLE];
        #pragma unroll
        for (int j = 0; j < 16; j++) {
            const int c4 = (tid & 15) + j*16;
            __half2 h0 = *(const __half2*)&S_h[row*S_STRH + c4*4    ];
            __half2 h1 = *(const __half2*)&S_h[row*S_STRH + c4*4 + 2];
            float2 f0 = __half22float2(h0);
            float2 f1 = __half22float2(h1);
            float4 p = {f0.x*inv, f0.y*inv, f1.x*inv, f1.y*inv};
            __stcs((float4*)&arow[c4*4], p);
        }
    }

    // ---- AV phase: direct V LDG, no barriers; warp w -> cols d in [w*8,+8) ----
    const __half* Vrow = Vth + ((size_t)bh*DK + w*8 + gid)*LLE;
    unsigned vf[8];
    #pragma unroll
    for (int ks = 0; ks < 4; ks++) {
        vf[ks*2    ] = *(const unsigned*)&Vrow[ks*16 + 2*tig    ];
        vf[ks*2 + 1] = *(const unsigned*)&Vrow[ks*16 + 2*tig + 8];
    }

    float av[4] = {0.0f, 0.0f, 0.0f, 0.0f};
    for (int t = 0; t < NTIL; t++) {
        unsigned vn[8];
        if (t + 1 < NTIL) {
            const __half* Vn = Vrow + (t + 1)*ST2;
            #pragma unroll
            for (int ks = 0; ks < 4; ks++) {
                vn[ks*2    ] = *(const unsigned*)&Vn[ks*16 + 2*tig    ];
                vn[ks*2 + 1] = *(const unsigned*)&Vn[ks*16 + 2*tig + 8];
            }
        }
        #pragma unroll
        for (int ks = 0; ks < 4; ks++) {
            const int kk = t*ST2 + ks*16;
            unsigned af[4];
            af[0] = *(const unsigned*)&S_h[ gid     *S_STRH + kk + 2*tig    ];
            af[1] = *(const unsigned*)&S_h[(gid + 8)*S_STRH + kk + 2*tig    ];
            af[2] = *(const unsigned*)&S_h[ gid     *S_STRH + kk + 2*tig + 8];
            af[3] = *(const unsigned*)&S_h[(gid + 8)*S_STRH + kk + 2*tig + 8];
            mma_f16(av, af, &vf[ks*2]);
        }
        #pragma unroll
        for (int i = 0; i < 8; i++) vf[i] = vn[i];
    }

    // write ctx (fp16, scaled by inv)
    {
        const float inv0 = invS[gid];
        const float inv1 = invS[gid + 8];
        const int cc = h*DK + w*8 + tig*2;
        const int r0 = b*LLE + qBase + gid;
        *(__half2*)&ctxh[(size_t)r0*DDIM + cc]     = __floats2half2_rn(av[0]*inv0, av[1]*inv0);
        *(__half2*)&ctxh[(size_t)(r0+8)*DDIM + cc] = __floats2half2_rn(av[2]*inv1, av[3]*inv1);
    }
}

// ---------------------------------------------------------------------------
extern "C" void kernel_launch(void* const* d_in, const int* in_sizes, int n_in,
                              void* d_out, int out_size)
{
    const float* query  = (const float*)d_in[0];
    const float* pos_b  = (const float*)d_in[1];
    const float* postag = (const float*)d_in[2];
    const float* lex    = (const float*)d_in[3];
    const int*   mask   = (const int*  )d_in[4];
    const float* Wq = (const float*)d_in[5];
    const float* bq = (const float*)d_in[6];
    const float* Wk = (const float*)d_in[7];
    const float* bk = (const float*)d_in[8];
    const float* Wv = (const float*)d_in[9];
    const float* bv = (const float*)d_in[10];
    const float* Wo = (const float*)d_in[11];
    const float* bo = (const float*)d_in[12];
    const float* gamma = (const float*)d_in[13];
    const float* beta  = (const float*)d_in[14];

    float* out  = (float*)d_out;             // (B,L,D)
    float* attn = (float*)d_out + OUT_ELEMS; // (B,H,L,L)

    __half* qnh  = nullptr; cudaGetSymbolAddress((void**)&qnh,  g_qnh);
    __half* xh   = nullptr; cudaGetSymbolAddress((void**)&xh,   g_xh);
    __half* Wh   = nullptr; cudaGetSymbolAddress((void**)&Wh,   g_wh);
    __half* Qh   = nullptr; cudaGetSymbolAddress((void**)&Qh,   g_qh);
    __half* Kh   = nullptr; cudaGetSymbolAddress((void**)&Kh,   g_kh);
    __half* Vth  = nullptr; cudaGetSymbolAddress((void**)&Vth,  g_vth);
    __half* ctxh = nullptr; cudaGetSymbolAddress((void**)&ctxh, g_ctxh);

    cudaFuncSetAttribute(attn_fused, cudaFuncAttributeMaxDynamicSharedMemorySize, SM_BYTES_A);

    // 1) pre-LN (emit qn fp16 + query fp16) and weight conversion
    ln_kernel<<<ROWS, 256>>>(query, gamma, beta, qnh, xh);
    cvt_w<<<dim3(1024, 4), 256>>>(Wq, Wk, Wv, Wo, Wh);

    // 2) Q/K/V projections (768 CTAs), fp16 in, fp16 out (V transposed)
    dim3 qkvGrid(DDIM/128, ROWS/64, 3);
    qkv_gemm<<<qkvGrid, 256>>>(qnh, xh, Wh, bq, bk, bv, Qh, Kh, Vth);

    // 3) fused logits + softmax + AV (barrier-free tiles)
    dim3 aGrid(LLE/QT, BB*HH);
    attn_fused<<<aGrid, 256, SM_BYTES_A>>>(Qh, Kh, Vth, pos_b, postag, lex, mask, attn, ctxh);

    // 4) out = ctx @ Wo^T + bo + residual(query)
    dim3 oGrid(DDIM/128, ROWS/64);
    out_gemm<<<oGrid, 256>>>(ctxh, Wh + (size_t)3*DDIM*DDIM, bo, query, out);
}